// round 10
// baseline (speedup 1.0000x reference)
#include <cuda_runtime.h>
#include <cuda_bf16.h>
#include <utility>

// DefocusBlur: depthwise 17x17 cross-correlation, reflect-101 borders.
// Input:  d_in[0] = float32 [32,3,512,512]; Output same shape.
//
// Byte-bound on the smem crossbar -> deep vertical strip (KPT=32) to
// amortize the 16-row halo: 102 B/output instead of 136.
//  * transposed smem tile (S[x][y], padded stride 50) -> LDS.64 loads a
//    vertical row-pair per column (17 loads per row-pair, conflict-free)
//  * ALL arithmetic scalar with compile-time immediate weights (FFMA-imm
//    rt=1; avoids the mov.b64 weight-pack ALU tax of packed FMA2)
//  * horizontal mirror symmetry: pair sums p[j]=v[8-j]+v[8+j]
//  * constant-interior box decomposition: blurred disk == CW on its whole
//    interior -> dot_D = CW*B[m_int(D)] + few corrections
//  * vertical mirror symmetry: row-dot D=dmin(dy) scattered to the 1-2
//    outputs that need it

struct WTab { float w[17][17]; };

__host__ __device__ constexpr WTab make_wtab() {
    WTab t{};
    const float g0 = 0.10650698f;
    const float g1 = 0.78698604f;
    const float g[3] = {g0, g1, g0};
    for (int i = 0; i < 17; ++i) {
        for (int j = 0; j < 17; ++j) {
            float s = 0.0f;
            for (int a = 0; a < 3; ++a) {
                for (int b = 0; b < 3; ++b) {
                    int r = i + a - 1;
                    int c = j + b - 1;
                    r = (r < 0) ? -r : ((r > 16) ? 32 - r : r);   // reflect-101
                    c = (c < 0) ? -c : ((c > 16) ? 32 - c : c);
                    const int dy = r - 8;
                    const int dx = c - 8;
                    if (dy * dy + dx * dx <= 64) s += g[a] * g[b];
                }
            }
            t.w[i][j] = s / 197.0f;
        }
    }
    WTab u{};   // symmetrize exactly (canonical quadrant copy)
    for (int i = 0; i < 17; ++i)
        for (int j = 0; j < 17; ++j) {
            const int ci = (i < 16 - i) ? i : 16 - i;
            const int cj = (j < 16 - j) ? j : 16 - j;
            u.w[i][j] = t.w[ci][cj];
        }
    return u;
}

constexpr WTab WT = make_wtab();
constexpr float CW = WT.w[8][8];   // interior constant (bit-exact on interior)

__host__ __device__ constexpr int dmin(int dy) { return (dy < 16 - dy) ? dy : 16 - dy; }

#define KPT    32                  // outputs per thread (vertical strip)
#define TILE_W 128
#define HALO   8
#define SMW    (TILE_W + 2 * HALO)   // 144 columns
#define SMH    48                    // rows incl halo (KPT + 16)
#define SMHP   50                    // padded column stride (even for 8B align;
                                     // odd in 8B units -> conflict-free LDS.64)
#define NTHREADS 128

// Largest M such that w[D][8+j] == CW for all j <= M (-1 if none).
__host__ __device__ constexpr int m_int(int D) {
    int m = -1;
    for (int j = 0; j <= 8; ++j) {
        if (WT.w[D][8 + j] == CW) m = j; else break;
    }
    return m;
}
__host__ __device__ constexpr int jfirst(int D) {
    for (int j = 0; j <= 8; ++j) if (WT.w[D][8 + j] != 0.0f) return j;
    return 9;
}
// Does row-pair M (local rows 2M, 2M+1) feed any output via weight-row D?
__host__ __device__ constexpr bool needD(int M, int D) {
    for (int dy = 0; dy <= 16; ++dy) {
        if (dmin(dy) != D) continue;
        const int kl = 2 * M - dy, kh = 2 * M + 1 - dy;
        if ((kl >= 0 && kl < KPT) || (kh >= 0 && kh < KPT)) return true;
    }
    return false;
}
// Deepest box index any needed D of row-pair M wants.
__host__ __device__ constexpr int maxM(int M) {
    int mm = -1;
    for (int D = 0; D <= 8; ++D)
        if (needD(M, D) && m_int(D) > mm) mm = m_int(D);
    return mm;
}
// Is tap J a correction tap for weight-row D?
// (beyond the constant-interior prefix; when no interior, jfirst seeds the
//  accumulator so it is excluded here)
__host__ __device__ constexpr bool is_corr(int D, int J) {
    const int MI = m_int(D);
    if (J <= MI) return false;
    if (MI < 0 && J == jfirst(D)) return false;
    return WT.w[D][8 + J] != 0.0f;
}

// ---- correction taps (both rows of the pair) ----
template <int D, int J>
__device__ __forceinline__ void corrtap(float& lo, float& hi,
                                        const float* pl, const float* ph) {
    if constexpr (is_corr(D, J)) {
        constexpr float w = WT.w[D][8 + J];
        lo = fmaf(pl[J], w, lo);
        hi = fmaf(ph[J], w, hi);
    }
}
template <int D, int... Js>
__device__ __forceinline__ void corrtaps(float& lo, float& hi,
                                         const float* pl, const float* ph,
                                         std::integer_sequence<int, Js...>) {
    (corrtap<D, Js>(lo, hi, pl, ph), ...);
}

// ---- scatter one dot's two halves into the strip's accumulators ----
template <int M, int D, int DY>
__device__ __forceinline__ void scat1(float* acc, float lo, float hi) {
    if constexpr (dmin(DY) == D) {
        constexpr int kl = 2 * M - DY;
        constexpr int kh = 2 * M + 1 - DY;
        if constexpr (kl >= 0 && kl < KPT) acc[kl] += lo;
        if constexpr (kh >= 0 && kh < KPT) acc[kh] += hi;
    }
}
template <int M, int D, int... DYs>
__device__ __forceinline__ void scat(float* acc, float lo, float hi,
                                     std::integer_sequence<int, DYs...>) {
    (scat1<M, D, DYs>(acc, lo, hi), ...);
}

// ---- one weight-row D: box + corrections, then scatter ----
template <int M, int D>
__device__ __forceinline__ void dodot(const float* pl, const float* ph,
                                      const float* Bl, const float* Bh,
                                      float* acc) {
    if constexpr (needD(M, D)) {
        constexpr int MI = m_int(D);
        float lo, hi;
        if constexpr (MI >= 0) {
            lo = CW * Bl[MI];
            hi = CW * Bh[MI];
        } else {
            constexpr int JF = jfirst(D);
            constexpr float wf = WT.w[D][8 + JF];
            lo = wf * pl[JF];
            hi = wf * ph[JF];
        }
        corrtaps<D>(lo, hi, pl, ph, std::make_integer_sequence<int, 9>{});
        scat<M, D>(acc, lo, hi, std::make_integer_sequence<int, 17>{});
    }
}
template <int M, int... Ds>
__device__ __forceinline__ void dodots(const float* pl, const float* ph,
                                       const float* Bl, const float* Bh,
                                       float* acc,
                                       std::integer_sequence<int, Ds...>) {
    (dodot<M, Ds>(pl, ph, Bl, Bh, acc), ...);
}

// ---- one input row-pair: 17 LDS.64 folded straight into pair sums ----
template <int M>
__device__ __forceinline__ void rowpair(const float* __restrict__ colbase,
                                        float* acc) {
    float pl[9], ph[9];
    {
        const float2 c = *reinterpret_cast<const float2*>(colbase + 8 * SMHP + 2 * M);
        pl[0] = c.x; ph[0] = c.y;
    }
    #pragma unroll
    for (int j = 1; j <= 8; ++j) {
        const float2 a = *reinterpret_cast<const float2*>(colbase + (8 - j) * SMHP + 2 * M);
        const float2 b = *reinterpret_cast<const float2*>(colbase + (8 + j) * SMHP + 2 * M);
        pl[j] = a.x + b.x;
        ph[j] = a.y + b.y;
    }
    float Bl[7], Bh[7];
    constexpr int MB = maxM(M);
    if constexpr (MB >= 0) {
        Bl[0] = pl[0]; Bh[0] = ph[0];
        #pragma unroll
        for (int m = 1; m <= MB; ++m) {
            Bl[m] = Bl[m - 1] + pl[m];
            Bh[m] = Bh[m - 1] + ph[m];
        }
    }
    dodots<M>(pl, ph, Bl, Bh, acc, std::make_integer_sequence<int, 9>{});
}
template <int... Ms>
__device__ __forceinline__ void rowpairs(const float* __restrict__ colbase,
                                         float* acc,
                                         std::integer_sequence<int, Ms...>) {
    (rowpair<Ms>(colbase, acc), ...);
}

__global__ void __launch_bounds__(NTHREADS, 5)
defocus_blur_kernel(const float* __restrict__ in, float* __restrict__ out) {
    __shared__ float S[SMW * SMHP];    // TRANSPOSED: S[x*SMHP + y]

    const int plane = blockIdx.z;                 // 0..95
    const int X0 = blockIdx.x * TILE_W;
    const int Y0 = blockIdx.y * KPT;

    const float* __restrict__ ip = in  + (size_t)plane * 512 * 512;
    float* __restrict__       op = out + (size_t)plane * 512 * 512;

    // ---- cooperative transposed tile load, reflect-101 (6912 elems) ----
    for (int idx = threadIdx.x; idx < SMH * SMW; idx += NTHREADS) {
        const int ly = idx / SMW;          // row    (gmem-coalesced in lx)
        const int lx = idx - ly * SMW;     // column
        int gy = Y0 - HALO + ly;
        gy = (gy < 0) ? -gy : ((gy > 511) ? 1022 - gy : gy);
        int gx = X0 - HALO + lx;
        gx = (gx < 0) ? -gx : ((gx > 511) ? 1022 - gx : gx);
        S[lx * SMHP + ly] = __ldg(&ip[gy * 512 + gx]);
    }
    __syncthreads();

    const int tx = threadIdx.x;          // output column within tile (0..127)

    float acc[KPT];
    #pragma unroll
    for (int k = 0; k < KPT; ++k) acc[k] = 0.0f;

    // Window columns tx..tx+16 (padded); rows 0..47 = 24 row-pairs.
    const float* colbase = &S[tx * SMHP];
    rowpairs(colbase, acc, std::make_integer_sequence<int, 24>{});

    // ---- store 32 output rows, coalesced 128-wide ----
    #pragma unroll
    for (int k = 0; k < KPT; ++k) {
        op[(Y0 + k) * 512 + X0 + tx] = acc[k];
    }
}

extern "C" void kernel_launch(void* const* d_in, const int* in_sizes, int n_in,
                              void* d_out, int out_size) {
    const float* in = (const float*)d_in[0];
    float* out = (float*)d_out;
    dim3 grid(512 / TILE_W, 512 / KPT, 96);   // 4 x 16 x 96 = 6144 blocks
    defocus_blur_kernel<<<grid, NTHREADS>>>(in, out);
}

// round 12
// speedup vs baseline: 1.2881x; 1.2881x over previous
#include <cuda_runtime.h>
#include <cuda_bf16.h>
#include <utility>

// DefocusBlur: depthwise 17x17 cross-correlation, reflect-101 borders.
// Input:  d_in[0] = float32 [32,3,512,512]; Output same shape.
//
// Round-6 engine (measured best: byte-bound at L1=92%), KPT 16->24 to cut
// smem-crossbar bytes/output 136 -> 113:
//  * transposed smem tile (S[x][y], padded stride 66) -> LDS.64 loads a
//    vertical row-pair per column, conflict-free (66 = odd in 8B units)
//  * packed f32x2 math: pair sums + row-dots for both rows in one slot
//  * horizontal mirror symmetry: pair sums p2[j]
//  * vertical mirror symmetry: row-dot D=dmin(dy) scattered to the <=2
//    outputs per half that need it
//  * KPT=24, 2 strips of 64 columns; grid.y=11 (partial last tile, stores
//    predicated; reflect handles the over-read rows)

using u64 = unsigned long long;

struct WTab { float w[17][17]; };

__host__ __device__ constexpr WTab make_wtab() {
    WTab t{};
    const float g0 = 0.10650698f;
    const float g1 = 0.78698604f;
    const float g[3] = {g0, g1, g0};
    for (int i = 0; i < 17; ++i) {
        for (int j = 0; j < 17; ++j) {
            float s = 0.0f;
            for (int a = 0; a < 3; ++a) {
                for (int b = 0; b < 3; ++b) {
                    int r = i + a - 1;
                    int c = j + b - 1;
                    r = (r < 0) ? -r : ((r > 16) ? 32 - r : r);   // reflect-101
                    c = (c < 0) ? -c : ((c > 16) ? 32 - c : c);
                    const int dy = r - 8;
                    const int dx = c - 8;
                    if (dy * dy + dx * dx <= 64) s += g[a] * g[b];
                }
            }
            t.w[i][j] = s / 197.0f;
        }
    }
    WTab u{};   // symmetrize exactly (canonical quadrant copy)
    for (int i = 0; i < 17; ++i)
        for (int j = 0; j < 17; ++j) {
            const int ci = (i < 16 - i) ? i : 16 - i;
            const int cj = (j < 16 - j) ? j : 16 - j;
            u.w[i][j] = t.w[ci][cj];
        }
    return u;
}

constexpr WTab WT = make_wtab();

__host__ __device__ constexpr int dmin(int dy) { return (dy < 16 - dy) ? dy : 16 - dy; }

#define KPT    24          // outputs per thread (vertical strip)
#define TILE_W 64
#define TILE_H 48          // 2 strips of KPT
#define HALO   8
#define SMW    80          // columns incl halo
#define SMH    64          // rows incl halo (TILE_H + 16)
#define SMHP   66          // padded column stride: even (8B align), 33 odd
                           // 8B units -> conflict-free LDS.64
#define NTHREADS 128       // 64 columns x 2 strips
#define NRP    ((KPT + 16) / 2)   // row-pairs per strip = 20

// Does row-pair M (local rows 2M, 2M+1) need weight-row D?
__host__ __device__ constexpr bool needD(int M, int D) {
    for (int dy = 0; dy <= 16; ++dy) {
        if (dmin(dy) != D) continue;
        const int kl = 2 * M - dy, kh = 2 * M + 1 - dy;
        if ((kl >= 0 && kl < KPT) || (kh >= 0 && kh < KPT)) return true;
    }
    return false;
}
__host__ __device__ constexpr int jfirst(int D) {
    for (int j = 0; j <= 8; ++j) if (WT.w[D][8 + j] != 0.0f) return j;
    return 9;
}

// ---- packed f32x2 primitives (sm_100a) ----
__device__ __forceinline__ u64 add2(u64 a, u64 b) {
    u64 d; asm("add.rn.f32x2 %0,%1,%2;" : "=l"(d) : "l"(a), "l"(b)); return d;
}
__device__ __forceinline__ u64 mul2(u64 a, u64 b) {
    u64 d; asm("mul.rn.f32x2 %0,%1,%2;" : "=l"(d) : "l"(a), "l"(b)); return d;
}
__device__ __forceinline__ u64 fma2(u64 a, u64 b, u64 c) {
    u64 d; asm("fma.rn.f32x2 %0,%1,%2,%3;" : "=l"(d) : "l"(a), "l"(b), "l"(c)); return d;
}
__device__ __forceinline__ u64 wpack(float w) {
    u64 r; asm("mov.b64 %0,{%1,%1};" : "=l"(r) : "f"(w)); return r;
}
__device__ __forceinline__ void unpack2(u64 v, float& lo, float& hi) {
    asm("mov.b64 {%0,%1},%2;" : "=f"(lo), "=f"(hi) : "l"(v));
}

// ---- dot taps (packed, weight broadcast) ----
template <int D, int J>
__device__ __forceinline__ void dtap(u64& s2, const u64* p2) {
    if constexpr (J > jfirst(D)) {
        constexpr float w = WT.w[D][8 + J];
        if constexpr (w != 0.0f) s2 = fma2(p2[J], wpack(w), s2);
    }
}
template <int D, int... Js>
__device__ __forceinline__ void dtaps(u64& s2, const u64* p2,
                                      std::integer_sequence<int, Js...>) {
    (dtap<D, Js>(s2, p2), ...);
}

// ---- scatter one dot's two halves into the scalar accumulators ----
template <int M, int D, int DY>
__device__ __forceinline__ void scat1(float* acc, float lo, float hi) {
    if constexpr (dmin(DY) == D) {
        constexpr int kl = 2 * M - DY;
        constexpr int kh = 2 * M + 1 - DY;
        if constexpr (kl >= 0 && kl < KPT) acc[kl] += lo;
        if constexpr (kh >= 0 && kh < KPT) acc[kh] += hi;
    }
}
template <int M, int D, int... DYs>
__device__ __forceinline__ void scat(float* acc, float lo, float hi,
                                     std::integer_sequence<int, DYs...>) {
    (scat1<M, D, DYs>(acc, lo, hi), ...);
}

template <int M, int D>
__device__ __forceinline__ void dodot(const u64* p2, float* acc) {
    if constexpr (needD(M, D)) {
        constexpr int JF = jfirst(D);
        u64 s2 = mul2(p2[JF], wpack(WT.w[D][8 + JF]));
        dtaps<D>(s2, p2, std::make_integer_sequence<int, 9>{});
        float lo, hi;
        unpack2(s2, lo, hi);
        scat<M, D>(acc, lo, hi, std::make_integer_sequence<int, 17>{});
    }
}
template <int M, int... Ds>
__device__ __forceinline__ void dodots(const u64* p2, float* acc,
                                       std::integer_sequence<int, Ds...>) {
    (dodot<M, Ds>(p2, acc), ...);
}

// ---- one row-pair: 17 LDS.64 + 8 ADD2 + packed dots + scalar scatter ----
template <int M>
__device__ __forceinline__ void rowpair(const float* __restrict__ colbase, float* acc) {
    // colbase = &S[tx * SMHP + rbase]; column dx at +dx*SMHP, rows 2M,2M+1 at +2M.
    u64 p2[9];
    p2[0] = *reinterpret_cast<const u64*>(colbase + 8 * SMHP + 2 * M);
    #pragma unroll
    for (int j = 1; j <= 8; ++j) {
        const u64 a = *reinterpret_cast<const u64*>(colbase + (8 - j) * SMHP + 2 * M);
        const u64 b = *reinterpret_cast<const u64*>(colbase + (8 + j) * SMHP + 2 * M);
        p2[j] = add2(a, b);
    }
    dodots<M>(p2, acc, std::make_integer_sequence<int, 9>{});
}

template <int... Ms>
__device__ __forceinline__ void rowpairs(const float* __restrict__ colbase, float* acc,
                                         std::integer_sequence<int, Ms...>) {
    (rowpair<Ms>(colbase, acc), ...);
}

__global__ void __launch_bounds__(NTHREADS, 8)
defocus_blur_kernel(const float* __restrict__ in, float* __restrict__ out) {
    __shared__ float S[SMW * SMHP];    // TRANSPOSED: S[x*SMHP + y]

    const int plane = blockIdx.z;                 // 0..95
    const int X0 = blockIdx.x * TILE_W;
    const int Y0 = blockIdx.y * TILE_H;           // last tile partial (528>512)

    const float* __restrict__ ip = in  + (size_t)plane * 512 * 512;
    float* __restrict__       op = out + (size_t)plane * 512 * 512;

    // ---- cooperative transposed tile load, reflect-101 (5120 elems) ----
    for (int idx = threadIdx.x; idx < SMH * SMW; idx += NTHREADS) {
        const int ly = idx / SMW;          // row    (gmem-coalesced in lx)
        const int lx = idx - ly * SMW;     // column
        int gy = Y0 - HALO + ly;           // <= 535, reflect stays valid
        gy = (gy < 0) ? -gy : ((gy > 511) ? 1022 - gy : gy);
        int gx = X0 - HALO + lx;
        gx = (gx < 0) ? -gx : ((gx > 511) ? 1022 - gx : gx);
        S[lx * SMHP + ly] = __ldg(&ip[gy * 512 + gx]);
    }
    __syncthreads();

    const int tx = threadIdx.x & 63;     // output column within tile
    const int ty = threadIdx.x >> 6;     // strip (0..1), KPT outputs each

    float acc[KPT];
    #pragma unroll
    for (int k = 0; k < KPT; ++k) acc[k] = 0.0f;

    // Strip covers padded rows [ty*KPT, ty*KPT + KPT+15] = NRP row-pairs.
    const float* colbase = &S[tx * SMHP + ty * KPT];
    rowpairs(colbase, acc, std::make_integer_sequence<int, NRP>{});

    // ---- store KPT output rows, coalesced 64-wide, y-predicated ----
    const int yo = Y0 + ty * KPT;
    #pragma unroll
    for (int k = 0; k < KPT; ++k) {
        if (yo + k < 512) {
            op[(yo + k) * 512 + X0 + tx] = acc[k];
        }
    }
}

extern "C" void kernel_launch(void* const* d_in, const int* in_sizes, int n_in,
                              void* d_out, int out_size) {
    const float* in = (const float*)d_in[0];
    float* out = (float*)d_out;
    dim3 grid(512 / TILE_W, (512 + TILE_H - 1) / TILE_H, 96);  // 8 x 11 x 96
    defocus_blur_kernel<<<grid, NTHREADS>>>(in, out);
}